// round 1
// baseline (speedup 1.0000x reference)
#include <cuda_runtime.h>
#include <cuda_bf16.h>
#include <math_constants.h>

// Problem constants (z: 32*2048*64 fp32, codebook: 1024*64 fp32)
#define N_VEC   65536
#define E_DIM   64
#define N_CODE  1024
#define CHUNK   128          // codes per smem chunk in argmin kernel
#define ELEMS   (N_VEC * E_DIM)   // 4194304

// Scratch (no allocations allowed)
__device__ float g_cc[N_CODE];          // ||e_j||^2
__device__ int   g_idx[N_VEC];
__device__ int   g_counts[N_CODE];
__device__ float g_sse_part[1024];

// ---- packed f32x2 helpers (Blackwell; PTX-only FFMA2 path) ----
__device__ __forceinline__ unsigned long long f32x2_fma(unsigned long long a,
                                                        unsigned long long b,
                                                        unsigned long long c) {
    unsigned long long d;
    asm("fma.rn.f32x2 %0, %1, %2, %3;" : "=l"(d) : "l"(a), "l"(b), "l"(c));
    return d;
}
__device__ __forceinline__ unsigned long long f32x2_add(unsigned long long a,
                                                        unsigned long long b) {
    unsigned long long d;
    asm("add.rn.f32x2 %0, %1, %2;" : "=l"(d) : "l"(a), "l"(b));
    return d;
}
__device__ __forceinline__ void f32x2_unpack(unsigned long long v, float& lo, float& hi) {
    unsigned int l, h;
    asm("mov.b64 {%0, %1}, %2;" : "=r"(l), "=r"(h) : "l"(v));
    lo = __uint_as_float(l);
    hi = __uint_as_float(h);
}

// ---------------------------------------------------------------------------
// Kernel 1: per-code squared norms + zero the histogram
// ---------------------------------------------------------------------------
__global__ void vq_prep(const float* __restrict__ cb) {
    int j = blockIdx.x * blockDim.x + threadIdx.x;
    if (j < N_CODE) {
        const float4* p = reinterpret_cast<const float4*>(cb + j * E_DIM);
        float s = 0.0f;
#pragma unroll
        for (int i = 0; i < E_DIM / 4; i++) {
            float4 v = p[i];
            s = fmaf(v.x, v.x, s);
            s = fmaf(v.y, v.y, s);
            s = fmaf(v.z, v.z, s);
            s = fmaf(v.w, v.w, s);
        }
        g_cc[j] = s;
        g_counts[j] = 0;
    }
}

// ---------------------------------------------------------------------------
// Kernel 2: argmin over codes (FMA-bound core), histogram, idx outputs
// One thread = one z vector held in registers; codebook chunks staged in smem
// and broadcast-read by the whole block.
// ---------------------------------------------------------------------------
__global__ void __launch_bounds__(256, 2)
vq_argmin(const float* __restrict__ z, const float* __restrict__ cb,
          float* __restrict__ out_idxf) {
    __shared__ float4 s_e[CHUNK * (E_DIM / 4)];   // 32 KB
    __shared__ float  s_cc[CHUNK];

    const int v = blockIdx.x * 256 + threadIdx.x;

    // Load this thread's z vector as 32 packed f32x2 values.
    unsigned long long zv[E_DIM / 2];
    {
        const ulonglong2* zp = reinterpret_cast<const ulonglong2*>(z + (size_t)v * E_DIM);
#pragma unroll
        for (int i = 0; i < E_DIM / 4; i++) {
            ulonglong2 t = zp[i];
            zv[2 * i]     = t.x;
            zv[2 * i + 1] = t.y;
        }
    }

    // zz = ||z||^2 (fp32; exact ordering irrelevant — see ulp-grid argument)
    float zz;
    {
        unsigned long long a0 = 0ull, a1 = 0ull;
#pragma unroll
        for (int i = 0; i < E_DIM / 2; i += 2) {
            a0 = f32x2_fma(zv[i], zv[i], a0);
            a1 = f32x2_fma(zv[i + 1], zv[i + 1], a1);
        }
        float lo, hi;
        f32x2_unpack(f32x2_add(a0, a1), lo, hi);
        zz = lo + hi;
    }

    float best = CUDART_INF_F;
    int bidx = 0;

    for (int c0 = 0; c0 < N_CODE; c0 += CHUNK) {
        __syncthreads();
        // cooperative, coalesced chunk load
        const float4* src = reinterpret_cast<const float4*>(cb + (size_t)c0 * E_DIM);
        for (int i = threadIdx.x; i < CHUNK * (E_DIM / 4); i += 256)
            s_e[i] = src[i];
        if (threadIdx.x < CHUNK)
            s_cc[threadIdx.x] = g_cc[c0 + threadIdx.x];
        __syncthreads();

        for (int j = 0; j < CHUNK; j++) {
            const ulonglong2* e =
                reinterpret_cast<const ulonglong2*>(s_e + j * (E_DIM / 4));
            unsigned long long acc0 = 0ull, acc1 = 0ull;
#pragma unroll
            for (int i = 0; i < E_DIM / 4; i++) {
                ulonglong2 t = e[i];                      // LDS.128 broadcast
                acc0 = f32x2_fma(zv[2 * i],     t.x, acc0);
                acc1 = f32x2_fma(zv[2 * i + 1], t.y, acc1);
            }
            float lo, hi;
            f32x2_unpack(f32x2_add(acc0, acc1), lo, hi);
            float dot = lo + hi;
            // Mirror reference rounding: fl( (zz + cc_j) - 2*dot )
            float d = fmaf(-2.0f, dot, zz + s_cc[j]);
            if (d < best) { best = d; bidx = c0 + j; }   // first-index tie-break
        }
    }

    g_idx[v] = bidx;
    out_idxf[v] = (float)bidx;

    // Block-local histogram (reuse s_e), then global atomics
    __syncthreads();
    int* hist = reinterpret_cast<int*>(s_e);
    for (int i = threadIdx.x; i < N_CODE; i += 256) hist[i] = 0;
    __syncthreads();
    atomicAdd(&hist[bidx], 1);
    __syncthreads();
    for (int i = threadIdx.x; i < N_CODE; i += 256) {
        int c = hist[i];
        if (c) atomicAdd(&g_counts[i], c);
    }
}

// ---------------------------------------------------------------------------
// Kernel 3: gather z_q, write straight-through output, SSE block partials
// Element-parallel, coalesced. 1024 blocks x 256 threads x 16 elems.
// ---------------------------------------------------------------------------
__global__ void vq_epilogue(const float* __restrict__ z, const float* __restrict__ cb,
                            float* __restrict__ out_zq) {
    float local = 0.0f;
    const int base = blockIdx.x * (256 * 16);
#pragma unroll
    for (int k = 0; k < 16; k++) {
        int e = base + k * 256 + threadIdx.x;
        int v = e >> 6;
        int d = e & 63;
        int ci = g_idx[v];
        float q  = cb[ci * E_DIM + d];
        float zf = z[e];
        float df = q - zf;
        local = fmaf(df, df, local);
        out_zq[e] = zf + (q - zf);   // mirror reference STE arithmetic exactly
    }
    __shared__ float red[256];
    red[threadIdx.x] = local;
    __syncthreads();
#pragma unroll
    for (int s = 128; s > 0; s >>= 1) {
        if (threadIdx.x < s) red[threadIdx.x] += red[threadIdx.x + s];
        __syncthreads();
    }
    if (threadIdx.x == 0) g_sse_part[blockIdx.x] = red[0];
}

// ---------------------------------------------------------------------------
// Kernel 4: finalize loss + perplexity
// ---------------------------------------------------------------------------
__global__ void vq_finalize(float* __restrict__ out) {
    __shared__ float red[1024];
    int t = threadIdx.x;

    // SSE reduction
    red[t] = g_sse_part[t];
    __syncthreads();
#pragma unroll
    for (int s = 512; s > 0; s >>= 1) {
        if (t < s) red[t] += red[t + s];
        __syncthreads();
    }
    float sse = red[0];
    __syncthreads();

    // entropy reduction
    float c = (float)g_counts[t];
    float em = c * (1.0f / (float)N_VEC);
    red[t] = em * logf(em + 1e-10f);
    __syncthreads();
#pragma unroll
    for (int s = 512; s > 0; s >>= 1) {
        if (t < s) red[t] += red[t + s];
        __syncthreads();
    }
    if (t == 0) {
        float mean = sse * (1.0f / (float)ELEMS);
        out[0] = 1.25f * mean;                 // (1 + BETA) * mean((z_q - z)^2)
        out[1 + ELEMS] = expf(-red[0]);        // perplexity
    }
}

// ---------------------------------------------------------------------------
// Launch: out layout = [loss(1) | z_q_st(N*64) | perplexity(1) | idx(N)]
// ---------------------------------------------------------------------------
extern "C" void kernel_launch(void* const* d_in, const int* in_sizes, int n_in,
                              void* d_out, int out_size) {
    const float* z  = (const float*)d_in[0];
    const float* cb = (const float*)d_in[1];
    float* out = (float*)d_out;

    float* out_zq   = out + 1;
    float* out_idxf = out + 2 + ELEMS;

    vq_prep<<<(N_CODE + 255) / 256, 256>>>(cb);
    vq_argmin<<<N_VEC / 256, 256>>>(z, cb, out_idxf);
    vq_epilogue<<<ELEMS / (256 * 16), 256>>>(z, cb, out_zq);
    vq_finalize<<<1, 1024>>>(out);
}

// round 3
// speedup vs baseline: 1.1112x; 1.1112x over previous
#include <cuda_runtime.h>
#include <cuda_bf16.h>
#include <math_constants.h>
#include <cstdint>

// Problem constants (z: 32*2048*64 fp32, codebook: 1024*64 fp32)
#define N_VEC   65536
#define E_DIM   64
#define N_CODE  1024
#define CHUNK   128                 // codes per smem chunk
#define ELEMS   (N_VEC * E_DIM)     // 4194304

#define THREADS 128
#define ROWS_PER_CTA 256            // 2 rows per thread
#define GRID_ARGMIN (N_VEC / ROWS_PER_CTA)   // 256

// Scratch (no allocations allowed)
__device__ float g_cc[N_CODE];
__device__ int   g_idx[N_VEC];
__device__ int   g_counts[N_CODE];
__device__ float g_sse_part[1024];

// ---- packed f32x2 helpers (Blackwell FFMA2; PTX-only) ----
__device__ __forceinline__ unsigned long long f32x2_fma(unsigned long long a,
                                                        unsigned long long b,
                                                        unsigned long long c) {
    unsigned long long d;
    asm("fma.rn.f32x2 %0, %1, %2, %3;" : "=l"(d) : "l"(a), "l"(b), "l"(c));
    return d;
}
__device__ __forceinline__ unsigned long long f32x2_add(unsigned long long a,
                                                        unsigned long long b) {
    unsigned long long d;
    asm("add.rn.f32x2 %0, %1, %2;" : "=l"(d) : "l"(a), "l"(b));
    return d;
}
__device__ __forceinline__ void f32x2_unpack(unsigned long long v, float& lo, float& hi) {
    unsigned int l, h;
    asm("mov.b64 {%0, %1}, %2;" : "=r"(l), "=r"(h) : "l"(v));
    lo = __uint_as_float(l);
    hi = __uint_as_float(h);
}

// ---------------------------------------------------------------------------
// Kernel 1: per-code squared norms + zero the histogram
// ---------------------------------------------------------------------------
__global__ void vq_prep(const float* __restrict__ cb) {
    int j = blockIdx.x * blockDim.x + threadIdx.x;
    if (j < N_CODE) {
        const float4* p = reinterpret_cast<const float4*>(cb + j * E_DIM);
        float s = 0.0f;
#pragma unroll
        for (int i = 0; i < E_DIM / 4; i++) {
            float4 v = p[i];
            s = fmaf(v.x, v.x, s);
            s = fmaf(v.y, v.y, s);
            s = fmaf(v.z, v.z, s);
            s = fmaf(v.w, v.w, s);
        }
        g_cc[j] = s;
        g_counts[j] = 0;
    }
}

// ---------------------------------------------------------------------------
// Kernel 2: argmin over codes, 2 rows per thread (FMA-pipe bound core)
//   Thread t owns rows base+t and base+t+128; codebook chunks staged in smem
//   and broadcast-read. The 16 LDS.128 per code amortize over 64 FFMA2.
// ---------------------------------------------------------------------------
__global__ void __launch_bounds__(THREADS, 3)
vq_argmin2(const float* __restrict__ z, const float* __restrict__ cb,
           float* __restrict__ out_idxf) {
    __shared__ float4 s_e[CHUNK * (E_DIM / 4)];   // 32 KB
    __shared__ float  s_cc[CHUNK];

    const int tid = threadIdx.x;
    const int r0 = blockIdx.x * ROWS_PER_CTA + tid;
    const int r1 = r0 + THREADS;

    // Load both z rows as packed f32x2 (32 regs each)
    unsigned long long zv0[E_DIM / 2], zv1[E_DIM / 2];
    {
        const ulonglong2* p0 = reinterpret_cast<const ulonglong2*>(z + (size_t)r0 * E_DIM);
        const ulonglong2* p1 = reinterpret_cast<const ulonglong2*>(z + (size_t)r1 * E_DIM);
#pragma unroll
        for (int i = 0; i < E_DIM / 4; i++) {
            ulonglong2 a = p0[i];
            zv0[2 * i] = a.x; zv0[2 * i + 1] = a.y;
            ulonglong2 b = p1[i];
            zv1[2 * i] = b.x; zv1[2 * i + 1] = b.y;
        }
    }

    // zz per row — identical accumulation pattern to the R1-passing kernel
    float zz0, zz1;
    {
        unsigned long long a0 = 0ull, a1 = 0ull, b0 = 0ull, b1 = 0ull;
#pragma unroll
        for (int i = 0; i < E_DIM / 2; i += 2) {
            a0 = f32x2_fma(zv0[i], zv0[i], a0);
            a1 = f32x2_fma(zv0[i + 1], zv0[i + 1], a1);
            b0 = f32x2_fma(zv1[i], zv1[i], b0);
            b1 = f32x2_fma(zv1[i + 1], zv1[i + 1], b1);
        }
        float lo, hi;
        f32x2_unpack(f32x2_add(a0, a1), lo, hi);
        zz0 = lo + hi;
        f32x2_unpack(f32x2_add(b0, b1), lo, hi);
        zz1 = lo + hi;
    }

    float best0 = CUDART_INF_F, best1 = CUDART_INF_F;
    int bidx0 = 0, bidx1 = 0;

    for (int c0 = 0; c0 < N_CODE; c0 += CHUNK) {
        __syncthreads();
        // cooperative, coalesced chunk load (128 codes x 64 floats = 2048 float4)
        const float4* src = reinterpret_cast<const float4*>(cb + (size_t)c0 * E_DIM);
#pragma unroll
        for (int k = 0; k < (CHUNK * (E_DIM / 4)) / THREADS; k++)
            s_e[k * THREADS + tid] = src[k * THREADS + tid];
        if (tid < CHUNK)
            s_cc[tid] = g_cc[c0 + tid];
        __syncthreads();

        for (int j = 0; j < CHUNK; j++) {
            const ulonglong2* e =
                reinterpret_cast<const ulonglong2*>(s_e + j * (E_DIM / 4));
            unsigned long long a0 = 0ull, a1 = 0ull;   // row 0
            unsigned long long b0 = 0ull, b1 = 0ull;   // row 1
#pragma unroll
            for (int i = 0; i < E_DIM / 4; i++) {
                ulonglong2 t = e[i];                   // LDS.128 broadcast
                a0 = f32x2_fma(zv0[2 * i],     t.x, a0);
                a1 = f32x2_fma(zv0[2 * i + 1], t.y, a1);
                b0 = f32x2_fma(zv1[2 * i],     t.x, b0);
                b1 = f32x2_fma(zv1[2 * i + 1], t.y, b1);
            }
            float lo, hi;
            f32x2_unpack(f32x2_add(a0, a1), lo, hi);
            float dot0 = lo + hi;
            f32x2_unpack(f32x2_add(b0, b1), lo, hi);
            float dot1 = lo + hi;
            float cc = s_cc[j];
            float d0 = fmaf(-2.0f, dot0, zz0 + cc);
            float d1 = fmaf(-2.0f, dot1, zz1 + cc);
            if (d0 < best0) { best0 = d0; bidx0 = c0 + j; }
            if (d1 < best1) { best1 = d1; bidx1 = c0 + j; }
        }
    }

    g_idx[r0] = bidx0;
    g_idx[r1] = bidx1;
    out_idxf[r0] = (float)bidx0;
    out_idxf[r1] = (float)bidx1;

    // Block-local histogram (reuse s_e), then global atomics
    __syncthreads();
    int* hist = reinterpret_cast<int*>(s_e);
    for (int i = tid; i < N_CODE; i += THREADS) hist[i] = 0;
    __syncthreads();
    atomicAdd(&hist[bidx0], 1);
    atomicAdd(&hist[bidx1], 1);
    __syncthreads();
    for (int i = tid; i < N_CODE; i += THREADS) {
        int c = hist[i];
        if (c) atomicAdd(&g_counts[i], c);
    }
}

// ---------------------------------------------------------------------------
// Kernel 3: gather z_q, STE output, SSE block partials
// ---------------------------------------------------------------------------
__global__ void vq_epilogue(const float* __restrict__ z, const float* __restrict__ cb,
                            float* __restrict__ out_zq) {
    float local = 0.0f;
    const int base = blockIdx.x * (256 * 16);
#pragma unroll
    for (int k = 0; k < 16; k++) {
        int e = base + k * 256 + threadIdx.x;
        int v = e >> 6;
        int d = e & 63;
        int ci = g_idx[v];
        float q  = cb[ci * E_DIM + d];
        float zf = z[e];
        float df = q - zf;
        local = fmaf(df, df, local);
        out_zq[e] = zf + (q - zf);   // mirror reference STE arithmetic
    }
    __shared__ float red[256];
    red[threadIdx.x] = local;
    __syncthreads();
#pragma unroll
    for (int s = 128; s > 0; s >>= 1) {
        if (threadIdx.x < s) red[threadIdx.x] += red[threadIdx.x + s];
        __syncthreads();
    }
    if (threadIdx.x == 0) g_sse_part[blockIdx.x] = red[0];
}

// ---------------------------------------------------------------------------
// Kernel 4: finalize loss + perplexity
// ---------------------------------------------------------------------------
__global__ void vq_finalize(float* __restrict__ out) {
    __shared__ float red[1024];
    int t = threadIdx.x;

    red[t] = g_sse_part[t];
    __syncthreads();
#pragma unroll
    for (int s = 512; s > 0; s >>= 1) {
        if (t < s) red[t] += red[t + s];
        __syncthreads();
    }
    float sse = red[0];
    __syncthreads();

    float c = (float)g_counts[t];
    float em = c * (1.0f / (float)N_VEC);
    red[t] = em * logf(em + 1e-10f);
    __syncthreads();
#pragma unroll
    for (int s = 512; s > 0; s >>= 1) {
        if (t < s) red[t] += red[t + s];
        __syncthreads();
    }
    if (t == 0) {
        float mean = sse * (1.0f / (float)ELEMS);
        out[0] = 1.25f * mean;             // (1 + BETA) * mean((z_q - z)^2)
        out[1 + ELEMS] = expf(-red[0]);    // perplexity
    }
}

// ---------------------------------------------------------------------------
// Launch: out layout = [loss(1) | z_q_st(N*64) | perplexity(1) | idx(N)]
// ---------------------------------------------------------------------------
extern "C" void kernel_launch(void* const* d_in, const int* in_sizes, int n_in,
                              void* d_out, int out_size) {
    const float* z  = (const float*)d_in[0];
    const float* cb = (const float*)d_in[1];
    float* out = (float*)d_out;

    float* out_zq   = out + 1;
    float* out_idxf = out + 2 + ELEMS;

    vq_prep<<<(N_CODE + 255) / 256, 256>>>(cb);
    vq_argmin2<<<GRID_ARGMIN, THREADS>>>(z, cb, out_idxf);
    vq_epilogue<<<ELEMS / (256 * 16), 256>>>(z, cb, out_zq);
    vq_finalize<<<1, 1024>>>(out);
}

// round 4
// speedup vs baseline: 1.2521x; 1.1269x over previous
#include <cuda_runtime.h>
#include <cuda_bf16.h>
#include <math_constants.h>
#include <cstdint>

// Problem constants (z: 32*2048*64 fp32, codebook: 1024*64 fp32)
#define N_VEC   65536
#define E_DIM   64
#define N_CODE  1024
#define ELEMS   (N_VEC * E_DIM)

#define TILE_M   128            // rows per screening CTA
#define CHUNK_N  64             // codes per screening chunk
#define NCHUNK   (N_CODE / CHUNK_N)   // 16
#define PAD      68             // u32 row stride in smem (conflict-free frags)
#define CAP      64             // candidate slots per row

// ---------------------------------------------------------------------------
// Global scratch (module globals; no runtime allocation)
// ---------------------------------------------------------------------------
__device__ float g_cc[N_CODE];
__device__ int   g_idx[N_VEC];
__device__ int   g_counts[N_CODE];
__device__ float g_sse_part[1024];
__device__ int   g_ccount[N_VEC];
__device__ int   g_over[N_VEC];
__device__ int   g_cand[N_VEC * CAP];      // 16 MB

// ---------------------------------------------------------------------------
// tf32 helpers
// ---------------------------------------------------------------------------
__device__ __forceinline__ uint32_t to_tf32(float x) {
    uint32_t r;
    asm("cvt.rna.tf32.f32 %0, %1;" : "=r"(r) : "f"(x));
    return r;
}

__device__ __forceinline__ void mma_m16n8k8_tf32(float* c, const uint32_t* a,
                                                 uint32_t b0, uint32_t b1) {
    asm volatile(
        "mma.sync.aligned.m16n8k8.row.col.f32.tf32.tf32.f32 "
        "{%0,%1,%2,%3}, {%4,%5,%6,%7}, {%8,%9}, {%0,%1,%2,%3};"
        : "+f"(c[0]), "+f"(c[1]), "+f"(c[2]), "+f"(c[3])
        : "r"(a[0]), "r"(a[1]), "r"(a[2]), "r"(a[3]), "r"(b0), "r"(b1));
}

// exact fp32 dot in the proven-safe float4 fmaf chain
__device__ __forceinline__ float dot64(const float4* __restrict__ a,
                                       const float4* __restrict__ b) {
    float s = 0.0f;
#pragma unroll
    for (int i = 0; i < 16; i++) {
        float4 x = a[i], y = b[i];
        s = fmaf(x.x, y.x, s);
        s = fmaf(x.y, y.y, s);
        s = fmaf(x.z, y.z, s);
        s = fmaf(x.w, y.w, s);
    }
    return s;
}

// ---------------------------------------------------------------------------
// Kernel 1: cc norms + zero all per-run state (graph-replay safe)
// ---------------------------------------------------------------------------
__global__ void vq_prep(const float* __restrict__ cb) {
    int bx = blockIdx.x, t = threadIdx.x;
    if (bx < 256) {
        int e = bx * 256 + t;          // 65536
        g_ccount[e] = 0;
        g_over[e] = 0;
    } else {
        int j = (bx - 256) * 256 + t;  // 1024
        if (j < N_CODE) {
            const float4* p = reinterpret_cast<const float4*>(cb + j * E_DIM);
            float s = 0.0f;
#pragma unroll
            for (int i = 0; i < 16; i++) {
                float4 v = p[i];
                s = fmaf(v.x, v.x, s);
                s = fmaf(v.y, v.y, s);
                s = fmaf(v.z, v.z, s);
                s = fmaf(v.w, v.w, s);
            }
            g_cc[j] = s;
            g_counts[j] = 0;
        }
    }
}

// ---------------------------------------------------------------------------
// Kernel 2: TF32 mma.sync screening + candidate emission
//   512 CTAs x 256 threads (8 warps). Warp w -> 16 rows. Chunks of 64 codes.
// ---------------------------------------------------------------------------
#define SM_A    0                          // u32[128*PAD]
#define SM_B    (TILE_M * PAD)             // u32[64*PAD]
#define SM_CC   (SM_B + CHUNK_N * PAD)     // float[1024]
#define SM_ZZ   (SM_CC + N_CODE)           // float[128]
#define SMEM_WORDS (SM_ZZ + TILE_M)

__global__ void __launch_bounds__(256, 2)
vq_screen(const float* __restrict__ z, const float* __restrict__ cb) {
    extern __shared__ uint32_t sm[];
    uint32_t* sA = sm + SM_A;
    uint32_t* sB = sm + SM_B;
    float* scc = reinterpret_cast<float*>(sm + SM_CC);
    float* szz = reinterpret_cast<float*>(sm + SM_ZZ);

    const int tid = threadIdx.x;
    const int lane = tid & 31;
    const int wid = tid >> 5;
    const int q = lane >> 2;        // 0..7
    const int t4 = lane & 3;        // 0..3
    const int tile0 = blockIdx.x * TILE_M;
    const int rg = wid * 16;        // this warp's row group (local)

    // stage A (z tile) as tf32, padded
    {
        const int r = tid >> 1;            // 0..127
        const int h = tid & 1;             // halves of 64 dims
        const float4* src = reinterpret_cast<const float4*>(
            z + (size_t)(tile0 + r) * E_DIM + h * 32);
        uint32_t* dst = sA + r * PAD + h * 32;
#pragma unroll
        for (int i = 0; i < 8; i++) {
            float4 v = src[i];
            dst[4 * i + 0] = to_tf32(v.x);
            dst[4 * i + 1] = to_tf32(v.y);
            dst[4 * i + 2] = to_tf32(v.z);
            dst[4 * i + 3] = to_tf32(v.w);
        }
    }
    // zz per row (exact fp32 chain)
    if (tid < TILE_M) {
        const float4* zr = reinterpret_cast<const float4*>(z + (size_t)(tile0 + tid) * E_DIM);
        float s = 0.0f;
#pragma unroll
        for (int i = 0; i < 16; i++) {
            float4 v = zr[i];
            s = fmaf(v.x, v.x, s);
            s = fmaf(v.y, v.y, s);
            s = fmaf(v.z, v.z, s);
            s = fmaf(v.w, v.w, s);
        }
        szz[tid] = s;
    }
    for (int i = tid; i < N_CODE; i += 256) scc[i] = g_cc[i];
    __syncthreads();

    // preload A fragments (persist across all chunks): 8 k-steps x 4 regs
    uint32_t af[8][4];
#pragma unroll
    for (int k = 0; k < 8; k++) {
        int c0 = k * 8 + t4;
        af[k][0] = sA[(rg + q) * PAD + c0];
        af[k][1] = sA[(rg + q + 8) * PAD + c0];
        af[k][2] = sA[(rg + q) * PAD + c0 + 4];
        af[k][3] = sA[(rg + q + 8) * PAD + c0 + 4];
    }
    const int row0 = tile0 + rg + q;
    const int row1 = row0 + 8;
    const float zz0 = szz[rg + q];
    const float zz1 = szz[rg + q + 8];
    const float margin0 = sqrtf(zz0) * 1e-4f + 5e-5f;
    const float margin1 = sqrtf(zz1) * 1e-4f + 5e-5f;

    float rmin0 = CUDART_INF_F, rmin1 = CUDART_INF_F;

    for (int c = 0; c < NCHUNK; c++) {
        __syncthreads();
        // stage B chunk (64 codes) as tf32, padded
        {
            const int jl = tid >> 2;                 // 0..63
            const int part = tid & 3;                // quarter of 64 dims
            const float4* src = reinterpret_cast<const float4*>(
                cb + (size_t)(c * CHUNK_N + jl) * E_DIM + part * 16);
            uint32_t* dst = sB + jl * PAD + part * 16;
#pragma unroll
            for (int i = 0; i < 4; i++) {
                float4 v = src[i];
                dst[4 * i + 0] = to_tf32(v.x);
                dst[4 * i + 1] = to_tf32(v.y);
                dst[4 * i + 2] = to_tf32(v.z);
                dst[4 * i + 3] = to_tf32(v.w);
            }
        }
        __syncthreads();

        float acc[8][4];
#pragma unroll
        for (int nb = 0; nb < 8; nb++) {
            acc[nb][0] = acc[nb][1] = acc[nb][2] = acc[nb][3] = 0.0f;
#pragma unroll
            for (int k = 0; k < 8; k++) {
                uint32_t b0 = sB[(nb * 8 + q) * PAD + k * 8 + t4];
                uint32_t b1 = sB[(nb * 8 + q) * PAD + k * 8 + t4 + 4];
                mma_m16n8k8_tf32(acc[nb], af[k], b0, b1);
            }
        }

        // convert to screened distances; track per-thread chunk mins
        float tmin0 = CUDART_INF_F, tmin1 = CUDART_INF_F;
#pragma unroll
        for (int nb = 0; nb < 8; nb++) {
            int jb = c * CHUNK_N + nb * 8 + 2 * t4;
            float cca = scc[jb], ccb = scc[jb + 1];
            float d0 = fmaf(-2.0f, acc[nb][0], zz0 + cca);
            float d1 = fmaf(-2.0f, acc[nb][1], zz0 + ccb);
            float d2 = fmaf(-2.0f, acc[nb][2], zz1 + cca);
            float d3 = fmaf(-2.0f, acc[nb][3], zz1 + ccb);
            acc[nb][0] = d0; acc[nb][1] = d1; acc[nb][2] = d2; acc[nb][3] = d3;
            tmin0 = fminf(tmin0, fminf(d0, d1));
            tmin1 = fminf(tmin1, fminf(d2, d3));
        }
        // quad reduce (lanes sharing a row differ in t4 only)
        tmin0 = fminf(tmin0, __shfl_xor_sync(0xffffffff, tmin0, 1));
        tmin0 = fminf(tmin0, __shfl_xor_sync(0xffffffff, tmin0, 2));
        tmin1 = fminf(tmin1, __shfl_xor_sync(0xffffffff, tmin1, 1));
        tmin1 = fminf(tmin1, __shfl_xor_sync(0xffffffff, tmin1, 2));
        rmin0 = fminf(rmin0, tmin0);
        rmin1 = fminf(rmin1, tmin1);
        const float th0 = rmin0 + margin0;
        const float th1 = rmin1 + margin1;

        // emit candidates within margin of running min
#pragma unroll
        for (int nb = 0; nb < 8; nb++) {
            int jb = c * CHUNK_N + nb * 8 + 2 * t4;
            if (acc[nb][0] <= th0) {
                int s = atomicAdd(&g_ccount[row0], 1);
                if (s < CAP) g_cand[row0 * CAP + s] = jb; else g_over[row0] = 1;
            }
            if (acc[nb][1] <= th0) {
                int s = atomicAdd(&g_ccount[row0], 1);
                if (s < CAP) g_cand[row0 * CAP + s] = jb + 1; else g_over[row0] = 1;
            }
            if (acc[nb][2] <= th1) {
                int s = atomicAdd(&g_ccount[row1], 1);
                if (s < CAP) g_cand[row1 * CAP + s] = jb; else g_over[row1] = 1;
            }
            if (acc[nb][3] <= th1) {
                int s = atomicAdd(&g_ccount[row1], 1);
                if (s < CAP) g_cand[row1 * CAP + s] = jb + 1; else g_over[row1] = 1;
            }
        }
    }
}

// ---------------------------------------------------------------------------
// Kernel 3: exact fp32 recheck of candidates; one warp per row
// ---------------------------------------------------------------------------
__global__ void __launch_bounds__(256)
vq_recheck(const float* __restrict__ z, const float* __restrict__ cb,
           float* __restrict__ out_idxf) {
    const int lane = threadIdx.x & 31;
    const int row = blockIdx.x * 8 + (threadIdx.x >> 5);

    // cache z row (uniform addresses -> broadcast loads)
    float4 zr[16];
    const float4* zp = reinterpret_cast<const float4*>(z + (size_t)row * E_DIM);
#pragma unroll
    for (int i = 0; i < 16; i++) zr[i] = zp[i];

    float zz = 0.0f;
#pragma unroll
    for (int i = 0; i < 16; i++) {
        float4 v = zr[i];
        zz = fmaf(v.x, v.x, zz);
        zz = fmaf(v.y, v.y, zz);
        zz = fmaf(v.z, v.z, zz);
        zz = fmaf(v.w, v.w, zz);
    }

    int n = g_ccount[row];
    bool full = (g_over[row] != 0) || (n > CAP);
    int n_eff = full ? N_CODE : n;

    unsigned long long best = 0xffffffffffffffffull;
    for (int i = lane; i < n_eff; i += 32) {
        int j = full ? i : g_cand[row * CAP + i];
        const float4* ep = reinterpret_cast<const float4*>(cb + (size_t)j * E_DIM);
        float dot = dot64(zr, ep);
        float d = fmaf(-2.0f, dot, zz + __ldg(&g_cc[j]));
        unsigned long long pk =
            ((unsigned long long)__float_as_uint(d) << 32) | (unsigned)j;
        best = min(best, pk);
    }
#pragma unroll
    for (int off = 16; off > 0; off >>= 1)
        best = min(best, __shfl_xor_sync(0xffffffff, best, off));

    if (lane == 0) {
        int bi = (int)(best & 0xffffffffu);
        g_idx[row] = bi;
        out_idxf[row] = (float)bi;
        atomicAdd(&g_counts[bi], 1);
    }
}

// ---------------------------------------------------------------------------
// Kernel 4: gather z_q, STE output, SSE block partials
// ---------------------------------------------------------------------------
__global__ void vq_epilogue(const float* __restrict__ z, const float* __restrict__ cb,
                            float* __restrict__ out_zq) {
    float local = 0.0f;
    const int base = blockIdx.x * (256 * 16);
#pragma unroll
    for (int k = 0; k < 16; k++) {
        int e = base + k * 256 + threadIdx.x;
        int v = e >> 6;
        int d = e & 63;
        int ci = g_idx[v];
        float qv = cb[ci * E_DIM + d];
        float zf = z[e];
        float df = qv - zf;
        local = fmaf(df, df, local);
        out_zq[e] = zf + (qv - zf);
    }
    __shared__ float red[256];
    red[threadIdx.x] = local;
    __syncthreads();
#pragma unroll
    for (int s = 128; s > 0; s >>= 1) {
        if (threadIdx.x < s) red[threadIdx.x] += red[threadIdx.x + s];
        __syncthreads();
    }
    if (threadIdx.x == 0) g_sse_part[blockIdx.x] = red[0];
}

// ---------------------------------------------------------------------------
// Kernel 5: finalize loss + perplexity
// ---------------------------------------------------------------------------
__global__ void vq_finalize(float* __restrict__ out) {
    __shared__ float red[1024];
    int t = threadIdx.x;

    red[t] = g_sse_part[t];
    __syncthreads();
#pragma unroll
    for (int s = 512; s > 0; s >>= 1) {
        if (t < s) red[t] += red[t + s];
        __syncthreads();
    }
    float sse = red[0];
    __syncthreads();

    float c = (float)g_counts[t];
    float em = c * (1.0f / (float)N_VEC);
    red[t] = em * logf(em + 1e-10f);
    __syncthreads();
#pragma unroll
    for (int s = 512; s > 0; s >>= 1) {
        if (t < s) red[t] += red[t + s];
        __syncthreads();
    }
    if (t == 0) {
        float mean = sse * (1.0f / (float)ELEMS);
        out[0] = 1.25f * mean;             // (1 + BETA) * mean((z_q - z)^2)
        out[1 + ELEMS] = expf(-red[0]);    // perplexity
    }
}

// ---------------------------------------------------------------------------
// Launch: out layout = [loss(1) | z_q_st(N*64) | perplexity(1) | idx(N)]
// ---------------------------------------------------------------------------
extern "C" void kernel_launch(void* const* d_in, const int* in_sizes, int n_in,
                              void* d_out, int out_size) {
    const float* z  = (const float*)d_in[0];
    const float* cb = (const float*)d_in[1];
    float* out = (float*)d_out;

    float* out_zq   = out + 1;
    float* out_idxf = out + 2 + ELEMS;

    static bool attr_set = false;
    if (!attr_set) {
        cudaFuncSetAttribute(vq_screen, cudaFuncAttributeMaxDynamicSharedMemorySize,
                             SMEM_WORDS * 4);
        attr_set = true;
    }

    vq_prep<<<260, 256>>>(cb);
    vq_screen<<<N_VEC / TILE_M, 256, SMEM_WORDS * 4>>>(z, cb);
    vq_recheck<<<N_VEC / 8, 256>>>(z, cb, out_idxf);
    vq_epilogue<<<ELEMS / (256 * 16), 256>>>(z, cb, out_zq);
    vq_finalize<<<1, 1024>>>(out);
}